// round 5
// baseline (speedup 1.0000x reference)
#include <cuda_runtime.h>
#include <cuda_bf16.h>
#include <cstdint>

// Problem constants (asserted by shapes in metadata: det[128,512,512] f32, tra[128,512,512] f32)
#define G_   128
#define MD   512
#define ND   512
#define DD   512
#define MA   513          // augmented dim
#define LDK  520          // padded row stride for EK scratch (float4-friendly)

// Scratch (static __device__ allocation - allowed; ~137 MB)
__device__ float g_EK[(size_t)G_ * MA * LDK];
__device__ float g_u[G_ * MA];
__device__ float g_v[G_ * MA];
__device__ float g_inv1[G_ * MD];   // 1/||tra_row||
__device__ float g_inv2[G_ * ND];   // 1/||det_row||

// ---------------------------------------------------------------------------
// Norms: one warp per feature row
// ---------------------------------------------------------------------------
__global__ void norms_kernel(const float* __restrict__ tra, const float* __restrict__ det) {
    int gw   = (blockIdx.x * blockDim.x + threadIdx.x) >> 5;
    int lane = threadIdx.x & 31;
    const float* src;
    float* dst;
    int row;
    if (gw < G_ * MD)            { src = tra; dst = g_inv1; row = gw; }
    else if (gw < 2 * G_ * MD)   { src = det; dst = g_inv2; row = gw - G_ * MD; }
    else return;
    const float4* p = reinterpret_cast<const float4*>(src + (size_t)row * DD);
    float s = 0.f;
#pragma unroll
    for (int k = 0; k < DD / 128; k++) {
        float4 v = p[lane + 32 * k];
        s += v.x * v.x + v.y * v.y + v.z * v.z + v.w * v.w;
    }
#pragma unroll
    for (int o = 16; o; o >>= 1) s += __shfl_xor_sync(0xffffffffu, s, o);
    if (lane == 0) dst[row] = rsqrtf(s);
}

// ---------------------------------------------------------------------------
// GEMM (bf16 mma.sync, fp32 accum) + epilogue: EK = exp(-cosine/lambda)
// C[g,m,n] = tra[g,m,:] . det[g,n,:]   (A row-major, B as [N,K] row-major -> col-major frag)
// Tile: CTA 128x128x32, 8 warps (2x4), warp 64x32
// ---------------------------------------------------------------------------
#define BK    32
#define LDS_S 40   // bf16 elems per smem row (80B, bank-conflict-free for ldmatrix)

__global__ void __launch_bounds__(256) gemm_ek_kernel(
    const float* __restrict__ tra, const float* __restrict__ det,
    const float* __restrict__ eps)
{
    __shared__ __nv_bfloat16 sA[128 * LDS_S];
    __shared__ __nv_bfloat16 sB[128 * LDS_S];

    int g  = blockIdx.z;
    int m0 = blockIdx.y * 128;
    int n0 = blockIdx.x * 128;
    const float* Ag = tra + (size_t)g * MD * DD + (size_t)m0 * DD;
    const float* Bg = det + (size_t)g * ND * DD + (size_t)n0 * DD;

    int tid  = threadIdx.x;
    int warp = tid >> 5, lane = tid & 31;
    int wm = (warp >> 2) * 64;   // warp row block (0 or 64)
    int wn = (warp & 3) * 32;    // warp col block (0..96)

    float acc[16][4];
#pragma unroll
    for (int i = 0; i < 16; i++)
#pragma unroll
        for (int j = 0; j < 4; j++) acc[i][j] = 0.f;

    int ldrow = tid >> 3;        // 0..31
    int ldc4  = tid & 7;         // 0..7 (float4 within 32-col slab)

    for (int k0 = 0; k0 < DD; k0 += BK) {
#pragma unroll
        for (int r = 0; r < 4; r++) {
            int row = ldrow + r * 32;
            float4 va = *reinterpret_cast<const float4*>(Ag + (size_t)row * DD + k0 + ldc4 * 4);
            float4 vb = *reinterpret_cast<const float4*>(Bg + (size_t)row * DD + k0 + ldc4 * 4);
            __nv_bfloat162* pa = reinterpret_cast<__nv_bfloat162*>(&sA[row * LDS_S + ldc4 * 4]);
            pa[0] = __floats2bfloat162_rn(va.x, va.y);
            pa[1] = __floats2bfloat162_rn(va.z, va.w);
            __nv_bfloat162* pb = reinterpret_cast<__nv_bfloat162*>(&sB[row * LDS_S + ldc4 * 4]);
            pb[0] = __floats2bfloat162_rn(vb.x, vb.y);
            pb[1] = __floats2bfloat162_rn(vb.z, vb.w);
        }
        __syncthreads();

#pragma unroll
        for (int kk = 0; kk < 2; kk++) {
            uint32_t afrag[4][4], bfrag[4][2];
#pragma unroll
            for (int mt = 0; mt < 4; mt++) {
                int row = wm + mt * 16 + (lane & 15);
                int col = kk * 16 + (lane >> 4) * 8;
                uint32_t addr = (uint32_t)__cvta_generic_to_shared(&sA[row * LDS_S + col]);
                asm volatile("ldmatrix.sync.aligned.m8n8.x4.shared.b16 {%0,%1,%2,%3}, [%4];"
                             : "=r"(afrag[mt][0]), "=r"(afrag[mt][1]),
                               "=r"(afrag[mt][2]), "=r"(afrag[mt][3])
                             : "r"(addr));
            }
#pragma unroll
            for (int nt = 0; nt < 4; nt++) {
                int row = wn + nt * 8 + (lane & 7);
                int col = kk * 16 + ((lane >> 3) & 1) * 8;
                uint32_t addr = (uint32_t)__cvta_generic_to_shared(&sB[row * LDS_S + col]);
                asm volatile("ldmatrix.sync.aligned.m8n8.x2.shared.b16 {%0,%1}, [%2];"
                             : "=r"(bfrag[nt][0]), "=r"(bfrag[nt][1])
                             : "r"(addr));
            }
#pragma unroll
            for (int mt = 0; mt < 4; mt++)
#pragma unroll
                for (int nt = 0; nt < 4; nt++) {
                    asm volatile(
                        "mma.sync.aligned.m16n8k16.row.col.f32.bf16.bf16.f32 "
                        "{%0,%1,%2,%3}, {%4,%5,%6,%7}, {%8,%9}, {%0,%1,%2,%3};"
                        : "+f"(acc[mt * 4 + nt][0]), "+f"(acc[mt * 4 + nt][1]),
                          "+f"(acc[mt * 4 + nt][2]), "+f"(acc[mt * 4 + nt][3])
                        : "r"(afrag[mt][0]), "r"(afrag[mt][1]),
                          "r"(afrag[mt][2]), "r"(afrag[mt][3]),
                          "r"(bfrag[nt][0]), "r"(bfrag[nt][1]));
                }
        }
        __syncthreads();
    }

    // Epilogue: EK = exp(-(acc * inv1 * inv2) / lambda)
    float inv_lam = 1.0f / (__expf(eps[0]) + 0.03f);
    float* EKg = g_EK + (size_t)g * MA * LDK;
#pragma unroll
    for (int mt = 0; mt < 4; mt++) {
#pragma unroll
        for (int nt = 0; nt < 4; nt++) {
            int mrow = m0 + wm + mt * 16 + (lane >> 2);
            int ncol = n0 + wn + nt * 8 + (lane & 3) * 2;
            float i1a = g_inv1[g * MD + mrow];
            float i1b = g_inv1[g * MD + mrow + 8];
            float i2a = g_inv2[g * ND + ncol];
            float i2b = g_inv2[g * ND + ncol + 1];
            float* p0 = EKg + (size_t)mrow * LDK + ncol;
            float* p1 = p0 + (size_t)8 * LDK;
            p0[0] = __expf(-acc[mt * 4 + nt][0] * i1a * i2a * inv_lam);
            p0[1] = __expf(-acc[mt * 4 + nt][1] * i1a * i2b * inv_lam);
            p1[0] = __expf(-acc[mt * 4 + nt][2] * i1b * i2a * inv_lam);
            p1[1] = __expf(-acc[mt * 4 + nt][3] * i1b * i2b * inv_lam);
        }
    }
}

// ---------------------------------------------------------------------------
// Fill augmented row/col of EK with exp(-alpha/lambda); init u = 1
// ---------------------------------------------------------------------------
__global__ void augment_kernel(const float* __restrict__ alpha, const float* __restrict__ eps) {
    int g = blockIdx.x;
    float lam = __expf(eps[0]) + 0.03f;
    float e = __expf(-alpha[0] / lam);
    float* EKg = g_EK + (size_t)g * MA * LDK;
    for (int j = threadIdx.x; j < MA; j += blockDim.x) {
        EKg[(size_t)(MA - 1) * LDK + j] = e;   // bottom augmented row
        EKg[(size_t)j * LDK + (MA - 1)] = e;   // right augmented col
        g_u[g * MA + j] = 1.0f;
    }
}

// ---------------------------------------------------------------------------
// Column step: v[j] = b[j] / sum_i EK[i,j]*u[i].   One thread per column.
// ---------------------------------------------------------------------------
__global__ void colsum_kernel() {
    __shared__ float su[MA + 7];
    int g = blockIdx.y;
    int j = blockIdx.x * blockDim.x + threadIdx.x;
    for (int i = threadIdx.x; i < MA; i += blockDim.x) su[i] = g_u[g * MA + i];
    __syncthreads();
    if (j >= MA) return;
    const float* p = g_EK + (size_t)g * MA * LDK + j;
    float s0 = 0.f, s1 = 0.f, s2 = 0.f, s3 = 0.f, s4 = 0.f, s5 = 0.f, s6 = 0.f, s7 = 0.f;
    int i = 0;
    for (; i + 8 <= MD; i += 8) {                 // 512 = 8*64; row 512 handled after
        s0 += p[(size_t)(i + 0) * LDK] * su[i + 0];
        s1 += p[(size_t)(i + 1) * LDK] * su[i + 1];
        s2 += p[(size_t)(i + 2) * LDK] * su[i + 2];
        s3 += p[(size_t)(i + 3) * LDK] * su[i + 3];
        s4 += p[(size_t)(i + 4) * LDK] * su[i + 4];
        s5 += p[(size_t)(i + 5) * LDK] * su[i + 5];
        s6 += p[(size_t)(i + 6) * LDK] * su[i + 6];
        s7 += p[(size_t)(i + 7) * LDK] * su[i + 7];
    }
    float s = ((s0 + s1) + (s2 + s3)) + ((s4 + s5) + (s6 + s7));
    s += p[(size_t)(MA - 1) * LDK] * su[MA - 1];
    float b = (j == MA - 1) ? 0.5f : (1.0f / 1024.0f);
    g_v[g * MA + j] = b / s;
}

// ---------------------------------------------------------------------------
// Row step: u[i] = a[i] / sum_j EK[i,j]*v[j].   One warp per row (float4 loads).
// ---------------------------------------------------------------------------
__global__ void rowsum_kernel() {
    __shared__ float sv[MA + 7];
    int g = blockIdx.y;
    for (int i = threadIdx.x; i < MA; i += blockDim.x) sv[i] = g_v[g * MA + i];
    __syncthreads();
    int warp = threadIdx.x >> 5, lane = threadIdx.x & 31;
    int i = blockIdx.x * 8 + warp;
    if (i >= MA) return;
    const float* row = g_EK + (size_t)g * MA * LDK + (size_t)i * LDK;
    const float4* r4 = reinterpret_cast<const float4*>(row);
    float s = 0.f;
#pragma unroll
    for (int k = 0; k < 4; k++) {                 // 512/4 = 128 float4 / 32 lanes
        int j4 = lane + 32 * k;
        float4 e = r4[j4];
        float4 w = *reinterpret_cast<const float4*>(&sv[4 * j4]);
        s += e.x * w.x + e.y * w.y + e.z * w.z + e.w * w.w;
    }
    if (lane == 0) s += row[MA - 1] * sv[MA - 1];
#pragma unroll
    for (int o = 16; o; o >>= 1) s += __shfl_xor_sync(0xffffffffu, s, o);
    if (lane == 0) {
        float a = (i == MA - 1) ? 0.5f : (1.0f / 1024.0f);
        g_u[g * MA + i] = a / s;
    }
}

// ---------------------------------------------------------------------------
// Final: out[g,i,j] = u[i] * EK[i,j] * v[j]  (packed 513x513)
// ---------------------------------------------------------------------------
__global__ void final_kernel(float* __restrict__ out) {
    int g = blockIdx.y;
    int idx = blockIdx.x * blockDim.x + threadIdx.x;
    if (idx >= MA * MA) return;
    int i = idx / MA;
    int j = idx - i * MA;
    float val = g_u[g * MA + i] *
                g_EK[(size_t)g * MA * LDK + (size_t)i * LDK + j] *
                g_v[g * MA + j];
    out[(size_t)g * MA * MA + idx] = val;
}

// ---------------------------------------------------------------------------
extern "C" void kernel_launch(void* const* d_in, const int* in_sizes, int n_in,
                              void* d_out, int out_size) {
    const float* det   = (const float*)d_in[0];  // [G, N, D]
    const float* tra   = (const float*)d_in[1];  // [G, M, D]
    const float* alpha = (const float*)d_in[2];
    const float* eps   = (const float*)d_in[3];
    float* out = (float*)d_out;
    (void)in_sizes; (void)n_in; (void)out_size;

    // norms: G*(M+N) rows, 1 warp each, 8 warps per 256-thread CTA
    norms_kernel<<<(G_ * (MD + ND)) / 8, 256>>>(tra, det);
    gemm_ek_kernel<<<dim3(ND / 128, MD / 128, G_), 256>>>(tra, det, eps);
    augment_kernel<<<G_, 256>>>(alpha, eps);

    for (int it = 0; it < 8; it++) {
        colsum_kernel<<<dim3((MA + 127) / 128, G_), 128>>>();
        rowsum_kernel<<<dim3((MA + 7) / 8, G_), 256>>>();
    }
    final_kernel<<<dim3((MA * MA + 255) / 256, G_), 256>>>(out);
}

// round 8
// speedup vs baseline: 1.4593x; 1.4593x over previous
#include <cuda_runtime.h>
#include <cuda_bf16.h>
#include <cuda_fp16.h>
#include <cstdint>

// Problem constants (det[128,512,512] f32, tra[128,512,512] f32)
#define G_   128
#define MD   512
#define ND   512
#define DD   512
#define MA   513          // augmented dim
#define LDK  520          // padded row stride for EK scratch (half2/uint4 friendly)

// Scratch (static __device__ allocation; EK in fp16 = ~68 MB, fits L2)
__device__ __half g_EKh[(size_t)G_ * MA * LDK];   // cols 513..519 stay zero (never written)
__device__ float g_u[G_ * MA];
__device__ float g_v[G_ * MA];
__device__ float g_inv1[G_ * MD];   // 1/||tra_row||
__device__ float g_inv2[G_ * ND];   // 1/||det_row||

// ---------------------------------------------------------------------------
// Norms: one warp per feature row
// ---------------------------------------------------------------------------
__global__ void norms_kernel(const float* __restrict__ tra, const float* __restrict__ det) {
    int gw   = (blockIdx.x * blockDim.x + threadIdx.x) >> 5;
    int lane = threadIdx.x & 31;
    const float* src;
    float* dst;
    int row;
    if (gw < G_ * MD)            { src = tra; dst = g_inv1; row = gw; }
    else if (gw < 2 * G_ * MD)   { src = det; dst = g_inv2; row = gw - G_ * MD; }
    else return;
    const float4* p = reinterpret_cast<const float4*>(src + (size_t)row * DD);
    float s = 0.f;
#pragma unroll
    for (int k = 0; k < DD / 128; k++) {
        float4 v = p[lane + 32 * k];
        s += v.x * v.x + v.y * v.y + v.z * v.z + v.w * v.w;
    }
#pragma unroll
    for (int o = 16; o; o >>= 1) s += __shfl_xor_sync(0xffffffffu, s, o);
    if (lane == 0) dst[row] = rsqrtf(s);
}

// ---------------------------------------------------------------------------
// GEMM (bf16 mma.sync, fp32 accum) + epilogue: EK = exp(-cosine/lambda) (fp16)
// Tile: CTA 128x128x32, 8 warps (2x4), warp 64x32
// ---------------------------------------------------------------------------
#define BK    32
#define LDS_S 40   // bf16 elems per smem row (80B)

__global__ void __launch_bounds__(256) gemm_ek_kernel(
    const float* __restrict__ tra, const float* __restrict__ det,
    const float* __restrict__ eps)
{
    __shared__ __nv_bfloat16 sA[128 * LDS_S];
    __shared__ __nv_bfloat16 sB[128 * LDS_S];

    int g  = blockIdx.z;
    int m0 = blockIdx.y * 128;
    int n0 = blockIdx.x * 128;
    const float* Ag = tra + (size_t)g * MD * DD + (size_t)m0 * DD;
    const float* Bg = det + (size_t)g * ND * DD + (size_t)n0 * DD;

    int tid  = threadIdx.x;
    int warp = tid >> 5, lane = tid & 31;
    int wm = (warp >> 2) * 64;
    int wn = (warp & 3) * 32;

    float acc[16][4];
#pragma unroll
    for (int i = 0; i < 16; i++)
#pragma unroll
        for (int j = 0; j < 4; j++) acc[i][j] = 0.f;

    int ldrow = tid >> 3;
    int ldc4  = tid & 7;

    for (int k0 = 0; k0 < DD; k0 += BK) {
#pragma unroll
        for (int r = 0; r < 4; r++) {
            int row = ldrow + r * 32;
            float4 va = *reinterpret_cast<const float4*>(Ag + (size_t)row * DD + k0 + ldc4 * 4);
            float4 vb = *reinterpret_cast<const float4*>(Bg + (size_t)row * DD + k0 + ldc4 * 4);
            __nv_bfloat162* pa = reinterpret_cast<__nv_bfloat162*>(&sA[row * LDS_S + ldc4 * 4]);
            pa[0] = __floats2bfloat162_rn(va.x, va.y);
            pa[1] = __floats2bfloat162_rn(va.z, va.w);
            __nv_bfloat162* pb = reinterpret_cast<__nv_bfloat162*>(&sB[row * LDS_S + ldc4 * 4]);
            pb[0] = __floats2bfloat162_rn(vb.x, vb.y);
            pb[1] = __floats2bfloat162_rn(vb.z, vb.w);
        }
        __syncthreads();

#pragma unroll
        for (int kk = 0; kk < 2; kk++) {
            uint32_t afrag[4][4], bfrag[4][2];
#pragma unroll
            for (int mt = 0; mt < 4; mt++) {
                int row = wm + mt * 16 + (lane & 15);
                int col = kk * 16 + (lane >> 4) * 8;
                uint32_t addr = (uint32_t)__cvta_generic_to_shared(&sA[row * LDS_S + col]);
                asm volatile("ldmatrix.sync.aligned.m8n8.x4.shared.b16 {%0,%1,%2,%3}, [%4];"
                             : "=r"(afrag[mt][0]), "=r"(afrag[mt][1]),
                               "=r"(afrag[mt][2]), "=r"(afrag[mt][3])
                             : "r"(addr));
            }
#pragma unroll
            for (int nt = 0; nt < 4; nt++) {
                int row = wn + nt * 8 + (lane & 7);
                int col = kk * 16 + ((lane >> 3) & 1) * 8;
                uint32_t addr = (uint32_t)__cvta_generic_to_shared(&sB[row * LDS_S + col]);
                asm volatile("ldmatrix.sync.aligned.m8n8.x2.shared.b16 {%0,%1}, [%2];"
                             : "=r"(bfrag[nt][0]), "=r"(bfrag[nt][1])
                             : "r"(addr));
            }
#pragma unroll
            for (int mt = 0; mt < 4; mt++)
#pragma unroll
                for (int nt = 0; nt < 4; nt++) {
                    asm volatile(
                        "mma.sync.aligned.m16n8k16.row.col.f32.bf16.bf16.f32 "
                        "{%0,%1,%2,%3}, {%4,%5,%6,%7}, {%8,%9}, {%0,%1,%2,%3};"
                        : "+f"(acc[mt * 4 + nt][0]), "+f"(acc[mt * 4 + nt][1]),
                          "+f"(acc[mt * 4 + nt][2]), "+f"(acc[mt * 4 + nt][3])
                        : "r"(afrag[mt][0]), "r"(afrag[mt][1]),
                          "r"(afrag[mt][2]), "r"(afrag[mt][3]),
                          "r"(bfrag[nt][0]), "r"(bfrag[nt][1]));
                }
        }
        __syncthreads();
    }

    // Epilogue: EK = exp(-(acc * inv1 * inv2) / lambda), stored fp16 as half2
    float inv_lam = 1.0f / (__expf(eps[0]) + 0.03f);
    __half* EKg = g_EKh + (size_t)g * MA * LDK;
#pragma unroll
    for (int mt = 0; mt < 4; mt++) {
#pragma unroll
        for (int nt = 0; nt < 4; nt++) {
            int mrow = m0 + wm + mt * 16 + (lane >> 2);
            int ncol = n0 + wn + nt * 8 + (lane & 3) * 2;
            float i1a = g_inv1[g * MD + mrow];
            float i1b = g_inv1[g * MD + mrow + 8];
            float i2a = g_inv2[g * ND + ncol];
            float i2b = g_inv2[g * ND + ncol + 1];
            float e00 = __expf(-acc[mt * 4 + nt][0] * i1a * i2a * inv_lam);
            float e01 = __expf(-acc[mt * 4 + nt][1] * i1a * i2b * inv_lam);
            float e10 = __expf(-acc[mt * 4 + nt][2] * i1b * i2a * inv_lam);
            float e11 = __expf(-acc[mt * 4 + nt][3] * i1b * i2b * inv_lam);
            __half2* q0 = reinterpret_cast<__half2*>(EKg + (size_t)mrow * LDK + ncol);
            __half2* q1 = reinterpret_cast<__half2*>(EKg + (size_t)(mrow + 8) * LDK + ncol);
            *q0 = __floats2half2_rn(e00, e01);
            *q1 = __floats2half2_rn(e10, e11);
        }
    }
}

// ---------------------------------------------------------------------------
// Fill augmented row/col of EK with exp(-alpha/lambda); init u = 1
// ---------------------------------------------------------------------------
__global__ void augment_kernel(const float* __restrict__ alpha, const float* __restrict__ eps) {
    int g = blockIdx.x;
    float lam = __expf(eps[0]) + 0.03f;
    __half e = __float2half(__expf(-alpha[0] / lam));
    __half* EKg = g_EKh + (size_t)g * MA * LDK;
    for (int j = threadIdx.x; j < MA; j += blockDim.x) {
        EKg[(size_t)(MA - 1) * LDK + j] = e;   // bottom augmented row
        EKg[(size_t)j * LDK + (MA - 1)] = e;   // right augmented col
        g_u[g * MA + j] = 1.0f;
    }
}

// ---------------------------------------------------------------------------
// Column step: v[j] = b[j] / sum_i EK[i,j]*u[i].
// 512 threads = 8 row-groups x 64 half2 column-pairs; smem partial combine.
// grid (5, G_): blockIdx.x covers 128 columns (last block: col 512 only).
// ---------------------------------------------------------------------------
__global__ void __launch_bounds__(512) colsum_kernel() {
    __shared__ float su[MA + 7];
    __shared__ float sp[8][132];
    int g = blockIdx.y;
    for (int i = threadIdx.x; i < MA; i += 512) su[i] = g_u[g * MA + i];
    __syncthreads();

    int tx = threadIdx.x & 63;    // half2 column-pair index within 128-col block
    int ty = threadIdx.x >> 6;    // row group 0..7 (64 rows each)
    int j0 = blockIdx.x * 128 + tx * 2;

    float a0 = 0.f, a1 = 0.f;
    if (j0 < MA) {   // j0==512 reads pair (512,513); col 513 is zero padding, discarded
        const __half2* p = reinterpret_cast<const __half2*>(
            g_EKh + (size_t)g * MA * LDK + j0);
        int r0 = ty * 64;
#pragma unroll 8
        for (int r = 0; r < 64; r++) {
            float2 e = __half22float2(p[(size_t)(r0 + r) * (LDK / 2)]);
            float uu = su[r0 + r];
            a0 += e.x * uu;
            a1 += e.y * uu;
        }
        if (ty == 0) {  // augmented row 512
            float2 e = __half22float2(p[(size_t)(MA - 1) * (LDK / 2)]);
            a0 += e.x * su[MA - 1];
            a1 += e.y * su[MA - 1];
        }
    }
    sp[ty][tx * 2]     = a0;
    sp[ty][tx * 2 + 1] = a1;
    __syncthreads();

    if (threadIdx.x < 128) {
        int j = blockIdx.x * 128 + threadIdx.x;
        if (j < MA) {
            float s = 0.f;
#pragma unroll
            for (int t = 0; t < 8; t++) s += sp[t][threadIdx.x];
            float b = (j == MA - 1) ? 0.5f : (1.0f / 1024.0f);
            g_v[g * MA + j] = b / s;
        }
    }
}

// ---------------------------------------------------------------------------
// Row step: u[i] = a[i] / sum_j EK[i,j]*v[j].  One warp per row, uint4 = 8 halves.
// ---------------------------------------------------------------------------
__global__ void rowsum_kernel() {
    __shared__ float sv[MA + 7];
    int g = blockIdx.y;
    for (int i = threadIdx.x; i < MA; i += blockDim.x) sv[i] = g_v[g * MA + i];
    __syncthreads();
    int warp = threadIdx.x >> 5, lane = threadIdx.x & 31;
    int i = blockIdx.x * 8 + warp;
    if (i >= MA) return;
    const __half* row = g_EKh + (size_t)g * MA * LDK + (size_t)i * LDK;
    float s = 0.f;
#pragma unroll
    for (int k = 0; k < 2; k++) {                 // 512 = 32 lanes * 8 halves * 2
        int j0 = (lane + 32 * k) * 8;
        uint4 raw = *reinterpret_cast<const uint4*>(row + j0);
        const __half2* h = reinterpret_cast<const __half2*>(&raw);
#pragma unroll
        for (int t = 0; t < 4; t++) {
            float2 f = __half22float2(h[t]);
            s += f.x * sv[j0 + 2 * t] + f.y * sv[j0 + 2 * t + 1];
        }
    }
    if (lane == 0) s += __half2float(row[MA - 1]) * sv[MA - 1];
#pragma unroll
    for (int o = 16; o; o >>= 1) s += __shfl_xor_sync(0xffffffffu, s, o);
    if (lane == 0) {
        float a = (i == MA - 1) ? 0.5f : (1.0f / 1024.0f);
        g_u[g * MA + i] = a / s;
    }
}

// ---------------------------------------------------------------------------
// Final: out[g,i,j] = u[i] * EK[i,j] * v[j]  (packed 513x513)
// ---------------------------------------------------------------------------
__global__ void final_kernel(float* __restrict__ out) {
    int g = blockIdx.y;
    int idx = blockIdx.x * blockDim.x + threadIdx.x;
    if (idx >= MA * MA) return;
    int i = idx / MA;
    int j = idx - i * MA;
    float val = g_u[g * MA + i] *
                __half2float(g_EKh[(size_t)g * MA * LDK + (size_t)i * LDK + j]) *
                g_v[g * MA + j];
    out[(size_t)g * MA * MA + idx] = val;
}

// ---------------------------------------------------------------------------
extern "C" void kernel_launch(void* const* d_in, const int* in_sizes, int n_in,
                              void* d_out, int out_size) {
    const float* det   = (const float*)d_in[0];  // [G, N, D]
    const float* tra   = (const float*)d_in[1];  // [G, M, D]
    const float* alpha = (const float*)d_in[2];
    const float* eps   = (const float*)d_in[3];
    float* out = (float*)d_out;
    (void)in_sizes; (void)n_in; (void)out_size;

    norms_kernel<<<(G_ * (MD + ND)) / 8, 256>>>(tra, det);
    gemm_ek_kernel<<<dim3(ND / 128, MD / 128, G_), 256>>>(tra, det, eps);
    augment_kernel<<<G_, 256>>>(alpha, eps);

    for (int it = 0; it < 8; it++) {
        colsum_kernel<<<dim3(5, G_), 512>>>();
        rowsum_kernel<<<dim3((MA + 7) / 8, G_), 256>>>();
    }
    final_kernel<<<dim3((MA * MA + 255) / 256, G_), 256>>>(out);
}

// round 12
// speedup vs baseline: 1.7127x; 1.1736x over previous
#include <cuda_runtime.h>
#include <cuda_bf16.h>
#include <cuda_fp16.h>
#include <cstdint>

#define G_   128
#define MD   512
#define ND   512
#define DD   512
#define MA   513          // augmented dim
#define LDK  520          // padded row stride (half2/uint4 friendly)

// EK in fp16 (~68 MB). Padding cols 513..519 stay zero (never written).
__device__ __half g_EKh[(size_t)G_ * MA * LDK];
__device__ float g_u[G_ * MA];
__device__ float g_v[G_ * MA];
__device__ float g_inv1[G_ * MD];
__device__ float g_inv2[G_ * ND];

// ---------------------------------------------------------------------------
// Norms: one warp per feature row
// ---------------------------------------------------------------------------
__global__ void norms_kernel(const float* __restrict__ tra, const float* __restrict__ det) {
    int gw   = (blockIdx.x * blockDim.x + threadIdx.x) >> 5;
    int lane = threadIdx.x & 31;
    const float* src;
    float* dst;
    int row;
    if (gw < G_ * MD)            { src = tra; dst = g_inv1; row = gw; }
    else if (gw < 2 * G_ * MD)   { src = det; dst = g_inv2; row = gw - G_ * MD; }
    else return;
    const float4* p = reinterpret_cast<const float4*>(src + (size_t)row * DD);
    float s = 0.f;
#pragma unroll
    for (int k = 0; k < DD / 128; k++) {
        float4 v = p[lane + 32 * k];
        s += v.x * v.x + v.y * v.y + v.z * v.z + v.w * v.w;
    }
#pragma unroll
    for (int o = 16; o; o >>= 1) s += __shfl_xor_sync(0xffffffffu, s, o);
    if (lane == 0) dst[row] = rsqrtf(s);
}

// ---------------------------------------------------------------------------
// GEMM (bf16 mma.sync, fp32 accum), double-buffered smem + register prefetch.
// CTA 128x128x32, 8 warps (2x4), warp 64x32. Epilogue: EK = exp(-cos/lambda) fp16.
// ---------------------------------------------------------------------------
#define BK    32
#define LDS_S 40   // bf16 elems per smem row (80B)

__global__ void __launch_bounds__(256) gemm_ek_kernel(
    const float* __restrict__ tra, const float* __restrict__ det,
    const float* __restrict__ eps)
{
    __shared__ __nv_bfloat16 sA[2][128 * LDS_S];
    __shared__ __nv_bfloat16 sB[2][128 * LDS_S];

    int g  = blockIdx.z;
    int m0 = blockIdx.y * 128;
    int n0 = blockIdx.x * 128;
    const float* Ag = tra + (size_t)g * MD * DD + (size_t)m0 * DD;
    const float* Bg = det + (size_t)g * ND * DD + (size_t)n0 * DD;

    int tid  = threadIdx.x;
    int warp = tid >> 5, lane = tid & 31;
    int wm = (warp >> 2) * 64;
    int wn = (warp & 3) * 32;

    float acc[16][4];
#pragma unroll
    for (int i = 0; i < 16; i++)
#pragma unroll
        for (int j = 0; j < 4; j++) acc[i][j] = 0.f;

    int ldrow = tid >> 3;
    int ldc4  = tid & 7;

    float4 ra[4], rb[4];

    // prolog: load tile 0 into regs, store to buf 0
#pragma unroll
    for (int r = 0; r < 4; r++) {
        int row = ldrow + r * 32;
        ra[r] = *reinterpret_cast<const float4*>(Ag + (size_t)row * DD + ldc4 * 4);
        rb[r] = *reinterpret_cast<const float4*>(Bg + (size_t)row * DD + ldc4 * 4);
    }
#pragma unroll
    for (int r = 0; r < 4; r++) {
        int row = ldrow + r * 32;
        __nv_bfloat162* pa = reinterpret_cast<__nv_bfloat162*>(&sA[0][row * LDS_S + ldc4 * 4]);
        pa[0] = __floats2bfloat162_rn(ra[r].x, ra[r].y);
        pa[1] = __floats2bfloat162_rn(ra[r].z, ra[r].w);
        __nv_bfloat162* pb = reinterpret_cast<__nv_bfloat162*>(&sB[0][row * LDS_S + ldc4 * 4]);
        pb[0] = __floats2bfloat162_rn(rb[r].x, rb[r].y);
        pb[1] = __floats2bfloat162_rn(rb[r].z, rb[r].w);
    }
    __syncthreads();

    for (int k0 = 0, it = 0; k0 < DD; k0 += BK, it++) {
        int cur = it & 1;
        bool has_next = (k0 + BK) < DD;
        if (has_next) {
#pragma unroll
            for (int r = 0; r < 4; r++) {
                int row = ldrow + r * 32;
                ra[r] = *reinterpret_cast<const float4*>(Ag + (size_t)row * DD + k0 + BK + ldc4 * 4);
                rb[r] = *reinterpret_cast<const float4*>(Bg + (size_t)row * DD + k0 + BK + ldc4 * 4);
            }
        }

#pragma unroll
        for (int kk = 0; kk < 2; kk++) {
            uint32_t afrag[4][4], bfrag[4][2];
#pragma unroll
            for (int mt = 0; mt < 4; mt++) {
                int row = wm + mt * 16 + (lane & 15);
                int col = kk * 16 + (lane >> 4) * 8;
                uint32_t addr = (uint32_t)__cvta_generic_to_shared(&sA[cur][row * LDS_S + col]);
                asm volatile("ldmatrix.sync.aligned.m8n8.x4.shared.b16 {%0,%1,%2,%3}, [%4];"
                             : "=r"(afrag[mt][0]), "=r"(afrag[mt][1]),
                               "=r"(afrag[mt][2]), "=r"(afrag[mt][3])
                             : "r"(addr));
            }
#pragma unroll
            for (int nt = 0; nt < 4; nt++) {
                int row = wn + nt * 8 + (lane & 7);
                int col = kk * 16 + ((lane >> 3) & 1) * 8;
                uint32_t addr = (uint32_t)__cvta_generic_to_shared(&sB[cur][row * LDS_S + col]);
                asm volatile("ldmatrix.sync.aligned.m8n8.x2.shared.b16 {%0,%1}, [%2];"
                             : "=r"(bfrag[nt][0]), "=r"(bfrag[nt][1])
                             : "r"(addr));
            }
#pragma unroll
            for (int mt = 0; mt < 4; mt++)
#pragma unroll
                for (int nt = 0; nt < 4; nt++) {
                    asm volatile(
                        "mma.sync.aligned.m16n8k16.row.col.f32.bf16.bf16.f32 "
                        "{%0,%1,%2,%3}, {%4,%5,%6,%7}, {%8,%9}, {%0,%1,%2,%3};"
                        : "+f"(acc[mt * 4 + nt][0]), "+f"(acc[mt * 4 + nt][1]),
                          "+f"(acc[mt * 4 + nt][2]), "+f"(acc[mt * 4 + nt][3])
                        : "r"(afrag[mt][0]), "r"(afrag[mt][1]),
                          "r"(afrag[mt][2]), "r"(afrag[mt][3]),
                          "r"(bfrag[nt][0]), "r"(bfrag[nt][1]));
                }
        }

        if (has_next) {
            int nxt = cur ^ 1;
#pragma unroll
            for (int r = 0; r < 4; r++) {
                int row = ldrow + r * 32;
                __nv_bfloat162* pa = reinterpret_cast<__nv_bfloat162*>(&sA[nxt][row * LDS_S + ldc4 * 4]);
                pa[0] = __floats2bfloat162_rn(ra[r].x, ra[r].y);
                pa[1] = __floats2bfloat162_rn(ra[r].z, ra[r].w);
                __nv_bfloat162* pb = reinterpret_cast<__nv_bfloat162*>(&sB[nxt][row * LDS_S + ldc4 * 4]);
                pb[0] = __floats2bfloat162_rn(rb[r].x, rb[r].y);
                pb[1] = __floats2bfloat162_rn(rb[r].z, rb[r].w);
            }
        }
        __syncthreads();
    }

    // Epilogue: EK = exp(-(acc * inv1 * inv2) / lambda), stored fp16 as half2
    float inv_lam = 1.0f / (__expf(eps[0]) + 0.03f);
    __half* EKg = g_EKh + (size_t)g * MA * LDK;
#pragma unroll
    for (int mt = 0; mt < 4; mt++) {
#pragma unroll
        for (int nt = 0; nt < 4; nt++) {
            int mrow = m0 + wm + mt * 16 + (lane >> 2);
            int ncol = n0 + wn + nt * 8 + (lane & 3) * 2;
            float i1a = g_inv1[g * MD + mrow];
            float i1b = g_inv1[g * MD + mrow + 8];
            float i2a = g_inv2[g * ND + ncol];
            float i2b = g_inv2[g * ND + ncol + 1];
            float e00 = __expf(-acc[mt * 4 + nt][0] * i1a * i2a * inv_lam);
            float e01 = __expf(-acc[mt * 4 + nt][1] * i1a * i2b * inv_lam);
            float e10 = __expf(-acc[mt * 4 + nt][2] * i1b * i2a * inv_lam);
            float e11 = __expf(-acc[mt * 4 + nt][3] * i1b * i2b * inv_lam);
            __half2* q0 = reinterpret_cast<__half2*>(EKg + (size_t)mrow * LDK + ncol);
            __half2* q1 = reinterpret_cast<__half2*>(EKg + (size_t)(mrow + 8) * LDK + ncol);
            *q0 = __floats2half2_rn(e00, e01);
            *q1 = __floats2half2_rn(e10, e11);
        }
    }
}

// ---------------------------------------------------------------------------
// Fill augmented row/col of EK; init u = 1
// ---------------------------------------------------------------------------
__global__ void augment_kernel(const float* __restrict__ alpha, const float* __restrict__ eps) {
    int g = blockIdx.x;
    float lam = __expf(eps[0]) + 0.03f;
    __half e = __float2half(__expf(-alpha[0] / lam));
    __half* EKg = g_EKh + (size_t)g * MA * LDK;
    for (int j = threadIdx.x; j < MA; j += blockDim.x) {
        EKg[(size_t)(MA - 1) * LDK + j] = e;
        EKg[(size_t)j * LDK + (MA - 1)] = e;
        g_u[g * MA + j] = 1.0f;
    }
}

// ---------------------------------------------------------------------------
// Column step: v[j] = b[j] / sum_i EK[i,j]*u[i].
// 256 threads = 32 row-groups (16 rows) x 8 col-octets (uint4 = 8 halves).
// grid (9, G_): blockIdx.x covers 64 columns.
// ---------------------------------------------------------------------------
__global__ void __launch_bounds__(256) colsum_kernel() {
    __shared__ __align__(16) float su[MA + 15];
    __shared__ float sp[32][64];
    int g = blockIdx.y;
    for (int i = threadIdx.x; i < MA; i += 256) su[i] = g_u[g * MA + i];
    __syncthreads();

    int c  = threadIdx.x & 7;     // col octet 0..7
    int ty = threadIdx.x >> 3;    // row group 0..31 (16 rows each)
    int j0 = blockIdx.x * 64 + c * 8;

    float s[8];
#pragma unroll
    for (int k = 0; k < 8; k++) s[k] = 0.f;

    if (j0 < MA) {
        const __half* base = g_EKh + (size_t)g * MA * LDK + j0;
        int r0 = ty * 16;
#pragma unroll
        for (int r = 0; r < 16; r++) {
            uint4 raw = *reinterpret_cast<const uint4*>(base + (size_t)(r0 + r) * LDK);
            const __half2* h = reinterpret_cast<const __half2*>(&raw);
            float uu = su[r0 + r];
#pragma unroll
            for (int t = 0; t < 4; t++) {
                float2 f = __half22float2(h[t]);
                s[2 * t]     += f.x * uu;
                s[2 * t + 1] += f.y * uu;
            }
        }
        if (ty == 0) {  // augmented row 512
            uint4 raw = *reinterpret_cast<const uint4*>(base + (size_t)(MA - 1) * LDK);
            const __half2* h = reinterpret_cast<const __half2*>(&raw);
            float uu = su[MA - 1];
#pragma unroll
            for (int t = 0; t < 4; t++) {
                float2 f = __half22float2(h[t]);
                s[2 * t]     += f.x * uu;
                s[2 * t + 1] += f.y * uu;
            }
        }
    }
#pragma unroll
    for (int k = 0; k < 8; k++) sp[ty][c * 8 + k] = s[k];
    __syncthreads();

    if (threadIdx.x < 64) {
        int j = blockIdx.x * 64 + threadIdx.x;
        if (j < MA) {
            float acc = 0.f;
#pragma unroll
            for (int t = 0; t < 32; t++) acc += sp[t][threadIdx.x];
            float b = (j == MA - 1) ? 0.5f : (1.0f / 1024.0f);
            g_v[g * MA + j] = b / acc;
        }
    }
}

// ---------------------------------------------------------------------------
// Row step: u[i] = a[i] / sum_j EK[i,j]*v[j].  One warp per row, uint4 loads.
// ---------------------------------------------------------------------------
__global__ void rowsum_kernel() {
    __shared__ __align__(16) float sv[MA + 15];
    int g = blockIdx.y;
    for (int i = threadIdx.x; i < MA; i += blockDim.x) sv[i] = g_v[g * MA + i];
    __syncthreads();
    int warp = threadIdx.x >> 5, lane = threadIdx.x & 31;
    int i = blockIdx.x * 8 + warp;
    if (i >= MA) return;
    const __half* row = g_EKh + (size_t)g * MA * LDK + (size_t)i * LDK;
    float s = 0.f;
#pragma unroll
    for (int k = 0; k < 2; k++) {
        int j0 = (lane + 32 * k) * 8;
        uint4 raw = *reinterpret_cast<const uint4*>(row + j0);
        const __half2* h = reinterpret_cast<const __half2*>(&raw);
        float4 w0 = *reinterpret_cast<const float4*>(&sv[j0]);
        float4 w1 = *reinterpret_cast<const float4*>(&sv[j0 + 4]);
        float2 f0 = __half22float2(h[0]);
        float2 f1 = __half22float2(h[1]);
        float2 f2 = __half22float2(h[2]);
        float2 f3 = __half22float2(h[3]);
        s += f0.x * w0.x + f0.y * w0.y + f1.x * w0.z + f1.y * w0.w;
        s += f2.x * w1.x + f2.y * w1.y + f3.x * w1.z + f3.y * w1.w;
    }
    if (lane == 0) s += __half2float(row[MA - 1]) * sv[MA - 1];
#pragma unroll
    for (int o = 16; o; o >>= 1) s += __shfl_xor_sync(0xffffffffu, s, o);
    if (lane == 0) {
        float a = (i == MA - 1) ? 0.5f : (1.0f / 1024.0f);
        g_u[g * MA + i] = a / s;
    }
}

// ---------------------------------------------------------------------------
// Final: out[g,i,j] = u[i] * EK[i,j] * v[j]  (packed 513x513)
// ---------------------------------------------------------------------------
__global__ void final_kernel(float* __restrict__ out) {
    int g = blockIdx.y;
    int idx = blockIdx.x * blockDim.x + threadIdx.x;
    if (idx >= MA * MA) return;
    int i = idx / MA;
    int j = idx - i * MA;
    float val = g_u[g * MA + i] *
                __half2float(g_EKh[(size_t)g * MA * LDK + (size_t)i * LDK + j]) *
                g_v[g * MA + j];
    out[(size_t)g * MA * MA + idx] = val;
}

// ---------------------------------------------------------------------------
extern "C" void kernel_launch(void* const* d_in, const int* in_sizes, int n_in,
                              void* d_out, int out_size) {
    const float* det   = (const float*)d_in[0];
    const float* tra   = (const float*)d_in[1];
    const float* alpha = (const float*)d_in[2];
    const float* eps   = (const float*)d_in[3];
    float* out = (float*)d_out;
    (void)in_sizes; (void)n_in; (void)out_size;

    norms_kernel<<<(G_ * (MD + ND)) / 8, 256>>>(tra, det);
    gemm_ek_kernel<<<dim3(ND / 128, MD / 128, G_), 256>>>(tra, det, eps);
    augment_kernel<<<G_, 256>>>(alpha, eps);

    for (int it = 0; it < 8; it++) {
        colsum_kernel<<<dim3(9, G_), 256>>>();
        rowsum_kernel<<<dim3((MA + 7) / 8, G_), 256>>>();
    }
    final_kernel<<<dim3((MA * MA + 255) / 256, G_), 256>>>(out);
}

// round 14
// speedup vs baseline: 1.8223x; 1.0640x over previous
#include <cuda_runtime.h>
#include <cuda_bf16.h>
#include <cuda_fp16.h>
#include <cstdint>

#define G_   128
#define MD   512
#define ND   512
#define DD   512
#define MA   513          // augmented dim
#define LDK  520          // padded row stride (half2/uint4 friendly)

// EK in fp16 (~68 MB). Padding cols 513..519 stay zero (never written).
__device__ __half g_EKh[(size_t)G_ * MA * LDK];
__device__ float g_u[G_ * MA];
__device__ float g_v[G_ * MA];
__device__ float g_inv1[G_ * MD];
__device__ float g_inv2[G_ * ND];

// ---------------------------------------------------------------------------
// Norms: one warp per feature row
// ---------------------------------------------------------------------------
__global__ void norms_kernel(const float* __restrict__ tra, const float* __restrict__ det) {
    int gw   = (blockIdx.x * blockDim.x + threadIdx.x) >> 5;
    int lane = threadIdx.x & 31;
    const float* src;
    float* dst;
    int row;
    if (gw < G_ * MD)            { src = tra; dst = g_inv1; row = gw; }
    else if (gw < 2 * G_ * MD)   { src = det; dst = g_inv2; row = gw - G_ * MD; }
    else return;
    const float4* p = reinterpret_cast<const float4*>(src + (size_t)row * DD);
    float s = 0.f;
#pragma unroll
    for (int k = 0; k < DD / 128; k++) {
        float4 v = p[lane + 32 * k];
        s += v.x * v.x + v.y * v.y + v.z * v.z + v.w * v.w;
    }
#pragma unroll
    for (int o = 16; o; o >>= 1) s += __shfl_xor_sync(0xffffffffu, s, o);
    if (lane == 0) dst[row] = rsqrtf(s);
}

// ---------------------------------------------------------------------------
// GEMM (bf16 mma.sync, fp32 accum), double-buffered smem + register prefetch.
// CTA 128x128x32, 8 warps (2x4), warp 64x32. Epilogue: EK = exp(-cos/lambda) fp16.
// ---------------------------------------------------------------------------
#define BK    32
#define LDS_S 40   // bf16 elems per smem row (80B)

__global__ void __launch_bounds__(256) gemm_ek_kernel(
    const float* __restrict__ tra, const float* __restrict__ det,
    const float* __restrict__ eps)
{
    __shared__ __nv_bfloat16 sA[2][128 * LDS_S];
    __shared__ __nv_bfloat16 sB[2][128 * LDS_S];

    int g  = blockIdx.z;
    int m0 = blockIdx.y * 128;
    int n0 = blockIdx.x * 128;
    const float* Ag = tra + (size_t)g * MD * DD + (size_t)m0 * DD;
    const float* Bg = det + (size_t)g * ND * DD + (size_t)n0 * DD;

    int tid  = threadIdx.x;
    int warp = tid >> 5, lane = tid & 31;
    int wm = (warp >> 2) * 64;
    int wn = (warp & 3) * 32;

    float acc[16][4];
#pragma unroll
    for (int i = 0; i < 16; i++)
#pragma unroll
        for (int j = 0; j < 4; j++) acc[i][j] = 0.f;

    int ldrow = tid >> 3;
    int ldc4  = tid & 7;

    float4 ra[4], rb[4];

    // prolog: load tile 0 into regs, store to buf 0
#pragma unroll
    for (int r = 0; r < 4; r++) {
        int row = ldrow + r * 32;
        ra[r] = *reinterpret_cast<const float4*>(Ag + (size_t)row * DD + ldc4 * 4);
        rb[r] = *reinterpret_cast<const float4*>(Bg + (size_t)row * DD + ldc4 * 4);
    }
#pragma unroll
    for (int r = 0; r < 4; r++) {
        int row = ldrow + r * 32;
        __nv_bfloat162* pa = reinterpret_cast<__nv_bfloat162*>(&sA[0][row * LDS_S + ldc4 * 4]);
        pa[0] = __floats2bfloat162_rn(ra[r].x, ra[r].y);
        pa[1] = __floats2bfloat162_rn(ra[r].z, ra[r].w);
        __nv_bfloat162* pb = reinterpret_cast<__nv_bfloat162*>(&sB[0][row * LDS_S + ldc4 * 4]);
        pb[0] = __floats2bfloat162_rn(rb[r].x, rb[r].y);
        pb[1] = __floats2bfloat162_rn(rb[r].z, rb[r].w);
    }
    __syncthreads();

    for (int k0 = 0, it = 0; k0 < DD; k0 += BK, it++) {
        int cur = it & 1;
        bool has_next = (k0 + BK) < DD;
        if (has_next) {
#pragma unroll
            for (int r = 0; r < 4; r++) {
                int row = ldrow + r * 32;
                ra[r] = *reinterpret_cast<const float4*>(Ag + (size_t)row * DD + k0 + BK + ldc4 * 4);
                rb[r] = *reinterpret_cast<const float4*>(Bg + (size_t)row * DD + k0 + BK + ldc4 * 4);
            }
        }

#pragma unroll
        for (int kk = 0; kk < 2; kk++) {
            uint32_t afrag[4][4], bfrag[4][2];
#pragma unroll
            for (int mt = 0; mt < 4; mt++) {
                int row = wm + mt * 16 + (lane & 15);
                int col = kk * 16 + (lane >> 4) * 8;
                uint32_t addr = (uint32_t)__cvta_generic_to_shared(&sA[cur][row * LDS_S + col]);
                asm volatile("ldmatrix.sync.aligned.m8n8.x4.shared.b16 {%0,%1,%2,%3}, [%4];"
                             : "=r"(afrag[mt][0]), "=r"(afrag[mt][1]),
                               "=r"(afrag[mt][2]), "=r"(afrag[mt][3])
                             : "r"(addr));
            }
#pragma unroll
            for (int nt = 0; nt < 4; nt++) {
                int row = wn + nt * 8 + (lane & 7);
                int col = kk * 16 + ((lane >> 3) & 1) * 8;
                uint32_t addr = (uint32_t)__cvta_generic_to_shared(&sB[cur][row * LDS_S + col]);
                asm volatile("ldmatrix.sync.aligned.m8n8.x2.shared.b16 {%0,%1}, [%2];"
                             : "=r"(bfrag[nt][0]), "=r"(bfrag[nt][1])
                             : "r"(addr));
            }
#pragma unroll
            for (int mt = 0; mt < 4; mt++)
#pragma unroll
                for (int nt = 0; nt < 4; nt++) {
                    asm volatile(
                        "mma.sync.aligned.m16n8k16.row.col.f32.bf16.bf16.f32 "
                        "{%0,%1,%2,%3}, {%4,%5,%6,%7}, {%8,%9}, {%0,%1,%2,%3};"
                        : "+f"(acc[mt * 4 + nt][0]), "+f"(acc[mt * 4 + nt][1]),
                          "+f"(acc[mt * 4 + nt][2]), "+f"(acc[mt * 4 + nt][3])
                        : "r"(afrag[mt][0]), "r"(afrag[mt][1]),
                          "r"(afrag[mt][2]), "r"(afrag[mt][3]),
                          "r"(bfrag[nt][0]), "r"(bfrag[nt][1]));
                }
        }

        if (has_next) {
            int nxt = cur ^ 1;
#pragma unroll
            for (int r = 0; r < 4; r++) {
                int row = ldrow + r * 32;
                __nv_bfloat162* pa = reinterpret_cast<__nv_bfloat162*>(&sA[nxt][row * LDS_S + ldc4 * 4]);
                pa[0] = __floats2bfloat162_rn(ra[r].x, ra[r].y);
                pa[1] = __floats2bfloat162_rn(ra[r].z, ra[r].w);
                __nv_bfloat162* pb = reinterpret_cast<__nv_bfloat162*>(&sB[nxt][row * LDS_S + ldc4 * 4]);
                pb[0] = __floats2bfloat162_rn(rb[r].x, rb[r].y);
                pb[1] = __floats2bfloat162_rn(rb[r].z, rb[r].w);
            }
        }
        __syncthreads();
    }

    // Epilogue: EK = exp(-(acc * inv1 * inv2) / lambda), stored fp16 as half2
    float inv_lam = 1.0f / (__expf(eps[0]) + 0.03f);
    __half* EKg = g_EKh + (size_t)g * MA * LDK;
#pragma unroll
    for (int mt = 0; mt < 4; mt++) {
#pragma unroll
        for (int nt = 0; nt < 4; nt++) {
            int mrow = m0 + wm + mt * 16 + (lane >> 2);
            int ncol = n0 + wn + nt * 8 + (lane & 3) * 2;
            float i1a = g_inv1[g * MD + mrow];
            float i1b = g_inv1[g * MD + mrow + 8];
            float i2a = g_inv2[g * ND + ncol];
            float i2b = g_inv2[g * ND + ncol + 1];
            float e00 = __expf(-acc[mt * 4 + nt][0] * i1a * i2a * inv_lam);
            float e01 = __expf(-acc[mt * 4 + nt][1] * i1a * i2b * inv_lam);
            float e10 = __expf(-acc[mt * 4 + nt][2] * i1b * i2a * inv_lam);
            float e11 = __expf(-acc[mt * 4 + nt][3] * i1b * i2b * inv_lam);
            __half2* q0 = reinterpret_cast<__half2*>(EKg + (size_t)mrow * LDK + ncol);
            __half2* q1 = reinterpret_cast<__half2*>(EKg + (size_t)(mrow + 8) * LDK + ncol);
            *q0 = __floats2half2_rn(e00, e01);
            *q1 = __floats2half2_rn(e10, e11);
        }
    }
}

// ---------------------------------------------------------------------------
// Fill augmented row/col of EK; init u = 1
// ---------------------------------------------------------------------------
__global__ void augment_kernel(const float* __restrict__ alpha, const float* __restrict__ eps) {
    int g = blockIdx.x;
    float lam = __expf(eps[0]) + 0.03f;
    __half e = __float2half(__expf(-alpha[0] / lam));
    __half* EKg = g_EKh + (size_t)g * MA * LDK;
    for (int j = threadIdx.x; j < MA; j += blockDim.x) {
        EKg[(size_t)(MA - 1) * LDK + j] = e;
        EKg[(size_t)j * LDK + (MA - 1)] = e;
        g_u[g * MA + j] = 1.0f;
    }
}

// ---------------------------------------------------------------------------
// Column step: v[j] = b[j] / sum_i EK[i,j]*u[i].
// 256 threads = 32 row-groups (16 rows) x 8 col-octets (uint4 = 8 halves).
// Loads batched 8-deep into a register staging array to force MLP~8/thread.
// grid (9, G_): blockIdx.x covers 64 columns.
// ---------------------------------------------------------------------------
__global__ void __launch_bounds__(256) colsum_kernel() {
    __shared__ __align__(16) float su[MA + 15];
    __shared__ float sp[32][64];
    int g = blockIdx.y;
    for (int i = threadIdx.x; i < MA; i += 256) su[i] = g_u[g * MA + i];
    __syncthreads();

    int c  = threadIdx.x & 7;     // col octet 0..7
    int ty = threadIdx.x >> 3;    // row group 0..31 (16 rows each)
    int j0 = blockIdx.x * 64 + c * 8;

    float s[8];
#pragma unroll
    for (int k = 0; k < 8; k++) s[k] = 0.f;

    if (j0 < MA) {
        const __half* base = g_EKh + (size_t)g * MA * LDK + j0;
        int r0 = ty * 16;
#pragma unroll
        for (int rb = 0; rb < 2; rb++) {
            uint4 raw[8];
#pragma unroll
            for (int r = 0; r < 8; r++)
                raw[r] = *reinterpret_cast<const uint4*>(base + (size_t)(r0 + rb * 8 + r) * LDK);
#pragma unroll
            for (int r = 0; r < 8; r++) {
                const __half2* h = reinterpret_cast<const __half2*>(&raw[r]);
                float uu = su[r0 + rb * 8 + r];
#pragma unroll
                for (int t = 0; t < 4; t++) {
                    float2 f = __half22float2(h[t]);
                    s[2 * t]     += f.x * uu;
                    s[2 * t + 1] += f.y * uu;
                }
            }
        }
        if (ty == 0) {  // augmented row 512
            uint4 raw = *reinterpret_cast<const uint4*>(base + (size_t)(MA - 1) * LDK);
            const __half2* h = reinterpret_cast<const __half2*>(&raw);
            float uu = su[MA - 1];
#pragma unroll
            for (int t = 0; t < 4; t++) {
                float2 f = __half22float2(h[t]);
                s[2 * t]     += f.x * uu;
                s[2 * t + 1] += f.y * uu;
            }
        }
    }
#pragma unroll
    for (int k = 0; k < 8; k++) sp[ty][c * 8 + k] = s[k];
    __syncthreads();

    if (threadIdx.x < 64) {
        int j = blockIdx.x * 64 + threadIdx.x;
        if (j < MA) {
            float acc = 0.f;
#pragma unroll
            for (int t = 0; t < 32; t++) acc += sp[t][threadIdx.x];
            float b = (j == MA - 1) ? 0.5f : (1.0f / 1024.0f);
            g_v[g * MA + j] = b / acc;
        }
    }
}

// ---------------------------------------------------------------------------
// Row step: u[i] = a[i] / sum_j EK[i,j]*v[j].  One warp per row, uint4 loads.
// ---------------------------------------------------------------------------
__global__ void rowsum_kernel() {
    __shared__ __align__(16) float sv[MA + 15];
    int g = blockIdx.y;
    for (int i = threadIdx.x; i < MA; i += blockDim.x) sv[i] = g_v[g * MA + i];
    __syncthreads();
    int warp = threadIdx.x >> 5, lane = threadIdx.x & 31;
    int i = blockIdx.x * 8 + warp;
    if (i >= MA) return;
    const __half* row = g_EKh + (size_t)g * MA * LDK + (size_t)i * LDK;
    float s = 0.f;
#pragma unroll
    for (int k = 0; k < 2; k++) {
        int j0 = (lane + 32 * k) * 8;
        uint4 raw = *reinterpret_cast<const uint4*>(row + j0);
        const __half2* h = reinterpret_cast<const __half2*>(&raw);
        float4 w0 = *reinterpret_cast<const float4*>(&sv[j0]);
        float4 w1 = *reinterpret_cast<const float4*>(&sv[j0 + 4]);
        float2 f0 = __half22float2(h[0]);
        float2 f1 = __half22float2(h[1]);
        float2 f2 = __half22float2(h[2]);
        float2 f3 = __half22float2(h[3]);
        s += f0.x * w0.x + f0.y * w0.y + f1.x * w0.z + f1.y * w0.w;
        s += f2.x * w1.x + f2.y * w1.y + f3.x * w1.z + f3.y * w1.w;
    }
    if (lane == 0) s += __half2float(row[MA - 1]) * sv[MA - 1];
#pragma unroll
    for (int o = 16; o; o >>= 1) s += __shfl_xor_sync(0xffffffffu, s, o);
    if (lane == 0) {
        float a = (i == MA - 1) ? 0.5f : (1.0f / 1024.0f);
        g_u[g * MA + i] = a / s;
    }
}

// ---------------------------------------------------------------------------
// Fused 8th row step + final output:
// u_i = a_i / sum_j EK[i,j]*v[j]; out[g,i,j] = u_i * EK[i,j] * v[j].
// EK row stays in registers; output staged through smem for coalesced stores.
// ---------------------------------------------------------------------------
__global__ void rowsum_final_kernel(float* __restrict__ out) {
    __shared__ __align__(16) float sv[MA + 15];
    __shared__ float sob[8][520];
    int g = blockIdx.y;
    for (int i = threadIdx.x; i < MA; i += blockDim.x) sv[i] = g_v[g * MA + i];
    __syncthreads();
    int warp = threadIdx.x >> 5, lane = threadIdx.x & 31;
    int i = blockIdx.x * 8 + warp;
    if (i >= MA) return;
    const __half* row = g_EKh + (size_t)g * MA * LDK + (size_t)i * LDK;

    uint4 raw0 = *reinterpret_cast<const uint4*>(row + lane * 8);
    uint4 raw1 = *reinterpret_cast<const uint4*>(row + (lane + 32) * 8);
    float ek512 = (lane == 0) ? __half2float(row[MA - 1]) : 0.f;

    float f[16];
    {
        const __half2* h0 = reinterpret_cast<const __half2*>(&raw0);
        const __half2* h1 = reinterpret_cast<const __half2*>(&raw1);
#pragma unroll
        for (int t = 0; t < 4; t++) {
            float2 a = __half22float2(h0[t]);
            f[2 * t] = a.x; f[2 * t + 1] = a.y;
            float2 b = __half22float2(h1[t]);
            f[8 + 2 * t] = b.x; f[8 + 2 * t + 1] = b.y;
        }
    }

    float s = 0.f;
    int ja = lane * 8, jb = (lane + 32) * 8;
#pragma unroll
    for (int t = 0; t < 8; t++) s += f[t] * sv[ja + t];
#pragma unroll
    for (int t = 0; t < 8; t++) s += f[8 + t] * sv[jb + t];
    if (lane == 0) s += ek512 * sv[MA - 1];
#pragma unroll
    for (int o = 16; o; o >>= 1) s += __shfl_xor_sync(0xffffffffu, s, o);

    float a_i = (i == MA - 1) ? 0.5f : (1.0f / 1024.0f);
    float ui = a_i / s;

    // products into smem row buffer
#pragma unroll
    for (int t = 0; t < 8; t++) sob[warp][ja + t] = ui * f[t] * sv[ja + t];
#pragma unroll
    for (int t = 0; t < 8; t++) sob[warp][jb + t] = ui * f[8 + t] * sv[jb + t];
    if (lane == 0) sob[warp][MA - 1] = ui * ek512 * sv[MA - 1];
    __syncwarp();

    float* orow = out + (size_t)g * MA * MA + (size_t)i * MA;
    for (int j = lane; j < MA; j += 32) orow[j] = sob[warp][j];
}

// ---------------------------------------------------------------------------
extern "C" void kernel_launch(void* const* d_in, const int* in_sizes, int n_in,
                              void* d_out, int out_size) {
    const float* det   = (const float*)d_in[0];
    const float* tra   = (const float*)d_in[1];
    const float* alpha = (const float*)d_in[2];
    const float* eps   = (const float*)d_in[3];
    float* out = (float*)d_out;
    (void)in_sizes; (void)n_in; (void)out_size;

    norms_kernel<<<(G_ * (MD + ND)) / 8, 256>>>(tra, det);
    gemm_ek_kernel<<<dim3(ND / 128, MD / 128, G_), 256>>>(tra, det, eps);
    augment_kernel<<<G_, 256>>>(alpha, eps);

    for (int it = 0; it < 8; it++) {
        colsum_kernel<<<dim3(9, G_), 256>>>();
        if (it < 7)
            rowsum_kernel<<<dim3((MA + 7) / 8, G_), 256>>>();
        else
            rowsum_final_kernel<<<dim3((MA + 7) / 8, G_), 256>>>(out);
    }
}

// round 17
// speedup vs baseline: 1.9329x; 1.0607x over previous
#include <cuda_runtime.h>
#include <cuda_bf16.h>
#include <cuda_fp16.h>
#include <cstdint>

#define G_   128
#define MD   512
#define ND   512
#define DD   512
#define MA   513          // augmented dim
#define LDK  520          // padded row stride (half2/uint4 friendly)

// EK in fp16 (~68 MB). Padding cols 513..519 stay zero (never written).
__device__ __half g_EKh[(size_t)G_ * MA * LDK];
__device__ float g_u[G_ * MA];
__device__ float g_v[G_ * MA];
__device__ float g_inv1[G_ * MD];
__device__ float g_inv2[G_ * ND];

// ---------------------------------------------------------------------------
// Norms: one warp per feature row
// ---------------------------------------------------------------------------
__global__ void norms_kernel(const float* __restrict__ tra, const float* __restrict__ det) {
    int gw   = (blockIdx.x * blockDim.x + threadIdx.x) >> 5;
    int lane = threadIdx.x & 31;
    const float* src;
    float* dst;
    int row;
    if (gw < G_ * MD)            { src = tra; dst = g_inv1; row = gw; }
    else if (gw < 2 * G_ * MD)   { src = det; dst = g_inv2; row = gw - G_ * MD; }
    else return;
    const float4* p = reinterpret_cast<const float4*>(src + (size_t)row * DD);
    float s = 0.f;
#pragma unroll
    for (int k = 0; k < DD / 128; k++) {
        float4 v = p[lane + 32 * k];
        s += v.x * v.x + v.y * v.y + v.z * v.z + v.w * v.w;
    }
#pragma unroll
    for (int o = 16; o; o >>= 1) s += __shfl_xor_sync(0xffffffffu, s, o);
    if (lane == 0) dst[row] = rsqrtf(s);
}

// ---------------------------------------------------------------------------
// GEMM (bf16 mma.sync, fp32 accum), double-buffered smem + register prefetch.
// CTA 128x128x32, 8 warps (2x4), warp 64x32. Epilogue: EK = exp(-cos/lambda) fp16.
// ---------------------------------------------------------------------------
#define BK    32
#define LDS_S 40   // bf16 elems per smem row (80B)

__global__ void __launch_bounds__(256) gemm_ek_kernel(
    const float* __restrict__ tra, const float* __restrict__ det,
    const float* __restrict__ eps)
{
    __shared__ __nv_bfloat16 sA[2][128 * LDS_S];
    __shared__ __nv_bfloat16 sB[2][128 * LDS_S];

    int g  = blockIdx.z;
    int m0 = blockIdx.y * 128;
    int n0 = blockIdx.x * 128;
    const float* Ag = tra + (size_t)g * MD * DD + (size_t)m0 * DD;
    const float* Bg = det + (size_t)g * ND * DD + (size_t)n0 * DD;

    int tid  = threadIdx.x;
    int warp = tid >> 5, lane = tid & 31;
    int wm = (warp >> 2) * 64;
    int wn = (warp & 3) * 32;

    float acc[16][4];
#pragma unroll
    for (int i = 0; i < 16; i++)
#pragma unroll
        for (int j = 0; j < 4; j++) acc[i][j] = 0.f;

    int ldrow = tid >> 3;
    int ldc4  = tid & 7;

    float4 ra[4], rb[4];

    // prolog: load tile 0 into regs, store to buf 0
#pragma unroll
    for (int r = 0; r < 4; r++) {
        int row = ldrow + r * 32;
        ra[r] = *reinterpret_cast<const float4*>(Ag + (size_t)row * DD + ldc4 * 4);
        rb[r] = *reinterpret_cast<const float4*>(Bg + (size_t)row * DD + ldc4 * 4);
    }
#pragma unroll
    for (int r = 0; r < 4; r++) {
        int row = ldrow + r * 32;
        __nv_bfloat162* pa = reinterpret_cast<__nv_bfloat162*>(&sA[0][row * LDS_S + ldc4 * 4]);
        pa[0] = __floats2bfloat162_rn(ra[r].x, ra[r].y);
        pa[1] = __floats2bfloat162_rn(ra[r].z, ra[r].w);
        __nv_bfloat162* pb = reinterpret_cast<__nv_bfloat162*>(&sB[0][row * LDS_S + ldc4 * 4]);
        pb[0] = __floats2bfloat162_rn(rb[r].x, rb[r].y);
        pb[1] = __floats2bfloat162_rn(rb[r].z, rb[r].w);
    }
    __syncthreads();

    for (int k0 = 0, it = 0; k0 < DD; k0 += BK, it++) {
        int cur = it & 1;
        bool has_next = (k0 + BK) < DD;
        if (has_next) {
#pragma unroll
            for (int r = 0; r < 4; r++) {
                int row = ldrow + r * 32;
                ra[r] = *reinterpret_cast<const float4*>(Ag + (size_t)row * DD + k0 + BK + ldc4 * 4);
                rb[r] = *reinterpret_cast<const float4*>(Bg + (size_t)row * DD + k0 + BK + ldc4 * 4);
            }
        }

#pragma unroll
        for (int kk = 0; kk < 2; kk++) {
            uint32_t afrag[4][4], bfrag[4][2];
#pragma unroll
            for (int mt = 0; mt < 4; mt++) {
                int row = wm + mt * 16 + (lane & 15);
                int col = kk * 16 + (lane >> 4) * 8;
                uint32_t addr = (uint32_t)__cvta_generic_to_shared(&sA[cur][row * LDS_S + col]);
                asm volatile("ldmatrix.sync.aligned.m8n8.x4.shared.b16 {%0,%1,%2,%3}, [%4];"
                             : "=r"(afrag[mt][0]), "=r"(afrag[mt][1]),
                               "=r"(afrag[mt][2]), "=r"(afrag[mt][3])
                             : "r"(addr));
            }
#pragma unroll
            for (int nt = 0; nt < 4; nt++) {
                int row = wn + nt * 8 + (lane & 7);
                int col = kk * 16 + ((lane >> 3) & 1) * 8;
                uint32_t addr = (uint32_t)__cvta_generic_to_shared(&sB[cur][row * LDS_S + col]);
                asm volatile("ldmatrix.sync.aligned.m8n8.x2.shared.b16 {%0,%1}, [%2];"
                             : "=r"(bfrag[nt][0]), "=r"(bfrag[nt][1])
                             : "r"(addr));
            }
#pragma unroll
            for (int mt = 0; mt < 4; mt++)
#pragma unroll
                for (int nt = 0; nt < 4; nt++) {
                    asm volatile(
                        "mma.sync.aligned.m16n8k16.row.col.f32.bf16.bf16.f32 "
                        "{%0,%1,%2,%3}, {%4,%5,%6,%7}, {%8,%9}, {%0,%1,%2,%3};"
                        : "+f"(acc[mt * 4 + nt][0]), "+f"(acc[mt * 4 + nt][1]),
                          "+f"(acc[mt * 4 + nt][2]), "+f"(acc[mt * 4 + nt][3])
                        : "r"(afrag[mt][0]), "r"(afrag[mt][1]),
                          "r"(afrag[mt][2]), "r"(afrag[mt][3]),
                          "r"(bfrag[nt][0]), "r"(bfrag[nt][1]));
                }
        }

        if (has_next) {
            int nxt = cur ^ 1;
#pragma unroll
            for (int r = 0; r < 4; r++) {
                int row = ldrow + r * 32;
                __nv_bfloat162* pa = reinterpret_cast<__nv_bfloat162*>(&sA[nxt][row * LDS_S + ldc4 * 4]);
                pa[0] = __floats2bfloat162_rn(ra[r].x, ra[r].y);
                pa[1] = __floats2bfloat162_rn(ra[r].z, ra[r].w);
                __nv_bfloat162* pb = reinterpret_cast<__nv_bfloat162*>(&sB[nxt][row * LDS_S + ldc4 * 4]);
                pb[0] = __floats2bfloat162_rn(rb[r].x, rb[r].y);
                pb[1] = __floats2bfloat162_rn(rb[r].z, rb[r].w);
            }
        }
        __syncthreads();
    }

    // Epilogue: EK = exp(-(acc * inv1 * inv2) / lambda), stored fp16 as half2
    float inv_lam = 1.0f / (__expf(eps[0]) + 0.03f);
    __half* EKg = g_EKh + (size_t)g * MA * LDK;
#pragma unroll
    for (int mt = 0; mt < 4; mt++) {
#pragma unroll
        for (int nt = 0; nt < 4; nt++) {
            int mrow = m0 + wm + mt * 16 + (lane >> 2);
            int ncol = n0 + wn + nt * 8 + (lane & 3) * 2;
            float i1a = g_inv1[g * MD + mrow];
            float i1b = g_inv1[g * MD + mrow + 8];
            float i2a = g_inv2[g * ND + ncol];
            float i2b = g_inv2[g * ND + ncol + 1];
            float e00 = __expf(-acc[mt * 4 + nt][0] * i1a * i2a * inv_lam);
            float e01 = __expf(-acc[mt * 4 + nt][1] * i1a * i2b * inv_lam);
            float e10 = __expf(-acc[mt * 4 + nt][2] * i1b * i2a * inv_lam);
            float e11 = __expf(-acc[mt * 4 + nt][3] * i1b * i2b * inv_lam);
            __half2* q0 = reinterpret_cast<__half2*>(EKg + (size_t)mrow * LDK + ncol);
            __half2* q1 = reinterpret_cast<__half2*>(EKg + (size_t)(mrow + 8) * LDK + ncol);
            *q0 = __floats2half2_rn(e00, e01);
            *q1 = __floats2half2_rn(e10, e11);
        }
    }
}

// ---------------------------------------------------------------------------
// Fill augmented row/col of EK; init u = 1
// ---------------------------------------------------------------------------
__global__ void augment_kernel(const float* __restrict__ alpha, const float* __restrict__ eps) {
    int g = blockIdx.x;
    float lam = __expf(eps[0]) + 0.03f;
    __half e = __float2half(__expf(-alpha[0] / lam));
    __half* EKg = g_EKh + (size_t)g * MA * LDK;
    for (int j = threadIdx.x; j < MA; j += blockDim.x) {
        EKg[(size_t)(MA - 1) * LDK + j] = e;
        EKg[(size_t)j * LDK + (MA - 1)] = e;
        g_u[g * MA + j] = 1.0f;
    }
}

// ---------------------------------------------------------------------------
// Column step: v[j] = b[j] / sum_i EK[i,j]*u[i].
// 256 threads = 32 row-groups (16 rows) x 8 col-octets (uint4 = 8 halves).
// (R12-measured variant: 16.7us, occ 89.6% — register staging reverted.)
// grid (9, G_): blockIdx.x covers 64 columns.
// ---------------------------------------------------------------------------
__global__ void __launch_bounds__(256) colsum_kernel() {
    __shared__ __align__(16) float su[MA + 15];
    __shared__ float sp[32][64];
    int g = blockIdx.y;
    for (int i = threadIdx.x; i < MA; i += 256) su[i] = g_u[g * MA + i];
    __syncthreads();

    int c  = threadIdx.x & 7;     // col octet 0..7
    int ty = threadIdx.x >> 3;    // row group 0..31 (16 rows each)
    int j0 = blockIdx.x * 64 + c * 8;

    float s[8];
#pragma unroll
    for (int k = 0; k < 8; k++) s[k] = 0.f;

    if (j0 < MA) {
        const __half* base = g_EKh + (size_t)g * MA * LDK + j0;
        int r0 = ty * 16;
#pragma unroll
        for (int r = 0; r < 16; r++) {
            uint4 raw = *reinterpret_cast<const uint4*>(base + (size_t)(r0 + r) * LDK);
            const __half2* h = reinterpret_cast<const __half2*>(&raw);
            float uu = su[r0 + r];
#pragma unroll
            for (int t = 0; t < 4; t++) {
                float2 f = __half22float2(h[t]);
                s[2 * t]     += f.x * uu;
                s[2 * t + 1] += f.y * uu;
            }
        }
        if (ty == 0) {  // augmented row 512
            uint4 raw = *reinterpret_cast<const uint4*>(base + (size_t)(MA - 1) * LDK);
            const __half2* h = reinterpret_cast<const __half2*>(&raw);
            float uu = su[MA - 1];
#pragma unroll
            for (int t = 0; t < 4; t++) {
                float2 f = __half22float2(h[t]);
                s[2 * t]     += f.x * uu;
                s[2 * t + 1] += f.y * uu;
            }
        }
    }
#pragma unroll
    for (int k = 0; k < 8; k++) sp[ty][c * 8 + k] = s[k];
    __syncthreads();

    if (threadIdx.x < 64) {
        int j = blockIdx.x * 64 + threadIdx.x;
        if (j < MA) {
            float acc = 0.f;
#pragma unroll
            for (int t = 0; t < 32; t++) acc += sp[t][threadIdx.x];
            float b = (j == MA - 1) ? 0.5f : (1.0f / 1024.0f);
            g_v[g * MA + j] = b / acc;
        }
    }
}

// ---------------------------------------------------------------------------
// Row step: u[i] = a[i] / sum_j EK[i,j]*v[j].  One warp per row, uint4 loads.
// ---------------------------------------------------------------------------
__global__ void rowsum_kernel() {
    __shared__ __align__(16) float sv[MA + 15];
    int g = blockIdx.y;
    for (int i = threadIdx.x; i < MA; i += blockDim.x) sv[i] = g_v[g * MA + i];
    __syncthreads();
    int warp = threadIdx.x >> 5, lane = threadIdx.x & 31;
    int i = blockIdx.x * 8 + warp;
    if (i >= MA) return;
    const __half* row = g_EKh + (size_t)g * MA * LDK + (size_t)i * LDK;
    float s = 0.f;
#pragma unroll
    for (int k = 0; k < 2; k++) {
        int j0 = (lane + 32 * k) * 8;
        uint4 raw = *reinterpret_cast<const uint4*>(row + j0);
        const __half2* h = reinterpret_cast<const __half2*>(&raw);
        float4 w0 = *reinterpret_cast<const float4*>(&sv[j0]);
        float4 w1 = *reinterpret_cast<const float4*>(&sv[j0 + 4]);
        float2 f0 = __half22float2(h[0]);
        float2 f1 = __half22float2(h[1]);
        float2 f2 = __half22float2(h[2]);
        float2 f3 = __half22float2(h[3]);
        s += f0.x * w0.x + f0.y * w0.y + f1.x * w0.z + f1.y * w0.w;
        s += f2.x * w1.x + f2.y * w1.y + f3.x * w1.z + f3.y * w1.w;
    }
    if (lane == 0) s += __half2float(row[MA - 1]) * sv[MA - 1];
#pragma unroll
    for (int o = 16; o; o >>= 1) s += __shfl_xor_sync(0xffffffffu, s, o);
    if (lane == 0) {
        float a = (i == MA - 1) ? 0.5f : (1.0f / 1024.0f);
        g_u[g * MA + i] = a / s;
    }
}

// ---------------------------------------------------------------------------
// Fused 8th row step + final output:
// u_i = a_i / sum_j EK[i,j]*v[j]; out[g,i,j] = u_i * EK[i,j] * v[j].
// EK row stays in registers; output staged through smem for coalesced stores.
// ---------------------------------------------------------------------------
__global__ void rowsum_final_kernel(float* __restrict__ out) {
    __shared__ __align__(16) float sv[MA + 15];
    __shared__ float sob[8][520];
    int g = blockIdx.y;
    for (int i = threadIdx.x; i < MA; i += blockDim.x) sv[i] = g_v[g * MA + i];
    __syncthreads();
    int warp = threadIdx.x >> 5, lane = threadIdx.x & 31;
    int i = blockIdx.x * 8 + warp;
    if (i >= MA) return;
    const __half* row = g_EKh + (size_t)g * MA * LDK + (size_t)i * LDK;

    uint4 raw0 = *reinterpret_cast<const uint4*>(row + lane * 8);
    uint4 raw1 = *reinterpret_cast<const uint4*>(row + (lane + 32) * 8);
    float ek512 = (lane == 0) ? __half2float(row[MA - 1]) : 0.f;

    float f[16];
    {
        const __half2* h0 = reinterpret_cast<const __half2*>(&raw0);
        const __half2* h1 = reinterpret_cast<const __half2*>(&raw1);
#pragma unroll
        for (int t = 0; t < 4; t++) {
            float2 a = __half22float2(h0[t]);
            f[2 * t] = a.x; f[2 * t + 1] = a.y;
            float2 b = __half22float2(h1[t]);
            f[8 + 2 * t] = b.x; f[8 + 2 * t + 1] = b.y;
        }
    }

    float s = 0.f;
    int ja = lane * 8, jb = (lane + 32) * 8;
#pragma unroll
    for (int t = 0; t < 8; t++) s += f[t] * sv[ja + t];
#pragma unroll
    for (int t = 0; t < 8; t++) s += f[8 + t] * sv[jb + t];
    if (lane == 0) s += ek512 * sv[MA - 1];
#pragma unroll
    for (int o = 16; o; o >>= 1) s += __shfl_xor_sync(0xffffffffu, s, o);

    float a_i = (i == MA - 1) ? 0.5f : (1.0f / 1024.0f);
    float ui = a_i / s;

    // products into smem row buffer
#pragma unroll
    for (int t = 0; t < 8; t++) sob[warp][ja + t] = ui * f[t] * sv[ja + t];
#pragma unroll
    for (int t = 0; t < 8; t++) sob[warp][jb + t] = ui * f[8 + t] * sv[jb + t];
    if (lane == 0) sob[warp][MA - 1] = ui * ek512 * sv[MA - 1];
    __syncwarp();

    float* orow = out + (size_t)g * MA * MA + (size_t)i * MA;
    for (int j = lane; j < MA; j += 32) orow[j] = sob[warp][j];
}

// ---------------------------------------------------------------------------
extern "C" void kernel_launch(void* const* d_in, const int* in_sizes, int n_in,
                              void* d_out, int out_size) {
    const float* det   = (const float*)d_in[0];
    const float* tra   = (const float*)d_in[1];
    const float* alpha = (const float*)d_in[2];
    const float* eps   = (const float*)d_in[3];
    float* out = (float*)d_out;
    (void)in_sizes; (void)n_in; (void)out_size;

    norms_kernel<<<(G_ * (MD + ND)) / 8, 256>>>(tra, det);
    gemm_ek_kernel<<<dim3(ND / 128, MD / 128, G_), 256>>>(tra, det, eps);
    augment_kernel<<<G_, 256>>>(alpha, eps);

    for (int it = 0; it < 8; it++) {
        colsum_kernel<<<dim3(9, G_), 256>>>();
        if (it < 7)
            rowsum_kernel<<<dim3((MA + 7) / 8, G_), 256>>>();
        else
            rowsum_final_kernel<<<dim3((MA + 7) / 8, G_), 256>>>(out);
    }
}